// round 1
// baseline (speedup 1.0000x reference)
#include <cuda_runtime.h>
#include <cuda_bf16.h>
#include <cstdint>
#include <cstddef>

// Problem constants (fixed-shape problem, verified against metadata sizes)
#define B_   4
#define S_   1024
#define T_   4096            // B*S
#define HID  4096
#define H_   32
#define KVH_ 8
#define D_   128
#define ROT_ 64
#define QKVW 6144            // H*D + 2*KVH*D
#define NSLOTS 8192
#define SCALE_ 0.08838834764831845f   // 1/sqrt(128)

// Scratch (allocation-free rule: __device__ globals)
__device__ float g_qkv[(size_t)T_ * QKVW];    // QKV projection output (RoPE applied in place)
__device__ float g_attn[(size_t)T_ * HID];    // attention output, pre-O-proj

// ---------------------------------------------------------------------------
// GEMM: C[M,N] = A[M,K] @ B[N,K]^T   (both operands K-contiguous row-major)
// 128x128 tile, BK=16, 256 threads, 8x8 micro-tile, register prefetch.
// ---------------------------------------------------------------------------
__global__ __launch_bounds__(256, 2) void gemm_abT(
    const float* __restrict__ A, const float* __restrict__ B,
    float* __restrict__ C, int M, int N, int K)
{
    __shared__ float As[16][132];
    __shared__ float Bs[16][132];
    const int tid = threadIdx.x;
    const int tx = tid & 15, ty = tid >> 4;
    const int bm = blockIdx.y << 7, bn = blockIdx.x << 7;
    const int lrow = tid >> 2;           // 0..63
    const int lcol = (tid & 3) << 2;     // 0,4,8,12

    const float* Ap = A + (size_t)(bm + lrow) * K + lcol;
    const float* Bp = B + (size_t)(bn + lrow) * K + lcol;

    float4 a0 = *(const float4*)(Ap);
    float4 a1 = *(const float4*)(Ap + (size_t)64 * K);
    float4 b0 = *(const float4*)(Bp);
    float4 b1 = *(const float4*)(Bp + (size_t)64 * K);

    float acc[8][8];
    #pragma unroll
    for (int i = 0; i < 8; ++i)
        #pragma unroll
        for (int j = 0; j < 8; ++j) acc[i][j] = 0.f;

    int k0 = 0;
    for (;;) {
        As[lcol + 0][lrow]      = a0.x; As[lcol + 1][lrow]      = a0.y;
        As[lcol + 2][lrow]      = a0.z; As[lcol + 3][lrow]      = a0.w;
        As[lcol + 0][lrow + 64] = a1.x; As[lcol + 1][lrow + 64] = a1.y;
        As[lcol + 2][lrow + 64] = a1.z; As[lcol + 3][lrow + 64] = a1.w;
        Bs[lcol + 0][lrow]      = b0.x; Bs[lcol + 1][lrow]      = b0.y;
        Bs[lcol + 2][lrow]      = b0.z; Bs[lcol + 3][lrow]      = b0.w;
        Bs[lcol + 0][lrow + 64] = b1.x; Bs[lcol + 1][lrow + 64] = b1.y;
        Bs[lcol + 2][lrow + 64] = b1.z; Bs[lcol + 3][lrow + 64] = b1.w;
        __syncthreads();

        k0 += 16;
        const bool more = (k0 < K);
        if (more) {  // prefetch next tile into registers, overlapped with compute
            a0 = *(const float4*)(Ap + k0);
            a1 = *(const float4*)(Ap + k0 + (size_t)64 * K);
            b0 = *(const float4*)(Bp + k0);
            b1 = *(const float4*)(Bp + k0 + (size_t)64 * K);
        }

        #pragma unroll
        for (int kk = 0; kk < 16; ++kk) {
            float ar[8], br[8];
            #pragma unroll
            for (int i = 0; i < 8; ++i) ar[i] = As[kk][(ty << 3) + i];
            #pragma unroll
            for (int j = 0; j < 8; ++j) br[j] = Bs[kk][(tx << 3) + j];
            #pragma unroll
            for (int i = 0; i < 8; ++i)
                #pragma unroll
                for (int j = 0; j < 8; ++j)
                    acc[i][j] = fmaf(ar[i], br[j], acc[i][j]);
        }
        __syncthreads();
        if (!more) break;
    }

    #pragma unroll
    for (int i = 0; i < 8; ++i) {
        const size_t row = (size_t)(bm + (ty << 3) + i);
        float* Cp = C + row * N + bn + (tx << 3);
        *(float4*)(Cp)     = make_float4(acc[i][0], acc[i][1], acc[i][2], acc[i][3]);
        *(float4*)(Cp + 4) = make_float4(acc[i][4], acc[i][5], acc[i][6], acc[i][7]);
    }
}

// ---------------------------------------------------------------------------
// RoPE, in place on q (heads 0..31) and k (heads 32..39) of g_qkv.
// ---------------------------------------------------------------------------
__global__ __launch_bounds__(256) void rope_kernel(
    float* __restrict__ qkv, const float* __restrict__ cs, const float* __restrict__ sn)
{
    int idx = blockIdx.x * 256 + threadIdx.x;      // T*40*64 threads
    int i = idx & 63;
    int head = (idx >> 6) % 40;                    // q heads then k heads (contiguous)
    int t = idx / (64 * 40);
    float* base = qkv + (size_t)t * QKVW + head * D_;
    float c = cs[t * ROT_ + i];
    float s = sn[t * ROT_ + i];
    float x1 = base[i];
    float x2 = base[i + ROT_];
    base[i]        = x1 * c - x2 * s;
    base[i + ROT_] = x1 * s + x2 * c;
}

// ---------------------------------------------------------------------------
// Scatter roped K and raw V into output caches (after D2D copy of inputs).
// ---------------------------------------------------------------------------
__global__ __launch_bounds__(256) void scatter_kv(
    const float* __restrict__ qkv, const int* __restrict__ slots,
    float* __restrict__ kc, float* __restrict__ vc)
{
    int t = blockIdx.x;
    int slot = slots[t];
    const float* k = qkv + (size_t)t * QKVW + (size_t)H_ * D_;
    const float* v = k + (size_t)KVH_ * D_;
    float* kd = kc + (size_t)slot * KVH_ * D_;
    float* vd = vc + (size_t)slot * KVH_ * D_;
    for (int i = threadIdx.x; i < KVH_ * D_; i += 256) {
        kd[i] = k[i];
        vd[i] = v[i];
    }
}

// ---------------------------------------------------------------------------
// Flash attention (fp32, online softmax). Block = one (b, h, 64-row q tile).
// 256 threads as 16x16: thread owns 4 q-rows x {4 score cols | 8 out cols}.
// ---------------------------------------------------------------------------
#define ATT_SMEM_FLOATS (64*132 + 128*65 + 64*132 + 64*68)

__global__ __launch_bounds__(256) void attn_kernel(
    const float* __restrict__ qkv, float* __restrict__ outa)
{
    extern __shared__ float sm[];
    float* Qs  = sm;                  // [64][132]
    float* KsT = Qs + 64 * 132;       // [128][65]  (K stored transposed)
    float* Vs  = KsT + 128 * 65;      // [64][132]
    float* Ps  = Vs + 64 * 132;       // [64][68]

    const int it = blockIdx.x;        // q tile 0..15
    const int h  = blockIdx.y;
    const int b  = blockIdx.z;
    const int kvh = h >> 2;           // groups = 4
    const int tid = threadIdx.x, tx = tid & 15, ty = tid >> 4;
    const int r0 = ty << 2;

    const float* qg = qkv + (size_t)(b * S_ + (it << 6)) * QKVW + h * D_;
    const float* kg = qkv + (size_t)(b * S_) * QKVW + (size_t)H_ * D_ + kvh * D_;
    const float* vg = kg + (size_t)KVH_ * D_;

    // Load Q tile (64 x 128)
    for (int i = tid; i < 2048; i += 256) {
        int r = i >> 5, c = (i & 31) << 2;
        *(float4*)(Qs + r * 132 + c) = *(const float4*)(qg + (size_t)r * QKVW + c);
    }

    float m[4], l[4], o[4][8];
    #pragma unroll
    for (int rr = 0; rr < 4; ++rr) {
        m[rr] = -1e30f; l[rr] = 0.f;
        #pragma unroll
        for (int j = 0; j < 8; ++j) o[rr][j] = 0.f;
    }

    for (int jt = 0; jt <= it; ++jt) {
        __syncthreads();   // previous PV done before overwriting K/V
        for (int i = tid; i < 2048; i += 256) {
            int r = i >> 5, c = (i & 31) << 2;
            float4 k4 = *(const float4*)(kg + (size_t)((jt << 6) + r) * QKVW + c);
            KsT[(c + 0) * 65 + r] = k4.x;
            KsT[(c + 1) * 65 + r] = k4.y;
            KsT[(c + 2) * 65 + r] = k4.z;
            KsT[(c + 3) * 65 + r] = k4.w;
            *(float4*)(Vs + r * 132 + c) =
                *(const float4*)(vg + (size_t)((jt << 6) + r) * QKVW + c);
        }
        __syncthreads();

        // S = Q K^T (4x4 per thread)
        float s[4][4];
        #pragma unroll
        for (int rr = 0; rr < 4; ++rr)
            #pragma unroll
            for (int cc = 0; cc < 4; ++cc) s[rr][cc] = 0.f;

        #pragma unroll 4
        for (int k = 0; k < 128; ++k) {
            float kr[4];
            #pragma unroll
            for (int cc = 0; cc < 4; ++cc) kr[cc] = KsT[k * 65 + (tx << 2) + cc];
            #pragma unroll
            for (int rr = 0; rr < 4; ++rr) {
                float qv = Qs[(r0 + rr) * 132 + k];
                #pragma unroll
                for (int cc = 0; cc < 4; ++cc)
                    s[rr][cc] = fmaf(qv, kr[cc], s[rr][cc]);
            }
        }

        const bool diag = (jt == it);
        #pragma unroll
        for (int rr = 0; rr < 4; ++rr) {
            float mx = -1e30f;
            #pragma unroll
            for (int cc = 0; cc < 4; ++cc) {
                float v = s[rr][cc] * SCALE_;
                if (diag && ((tx << 2) + cc > r0 + rr)) v = -1e30f;
                s[rr][cc] = v;
                mx = fmaxf(mx, v);
            }
            #pragma unroll
            for (int off = 8; off; off >>= 1)
                mx = fmaxf(mx, __shfl_xor_sync(0xffffffffu, mx, off));
            float mnew = fmaxf(m[rr], mx);
            float alpha = __expf(m[rr] - mnew);
            float lsum = 0.f;
            #pragma unroll
            for (int cc = 0; cc < 4; ++cc) {
                float p = __expf(s[rr][cc] - mnew);
                s[rr][cc] = p;
                lsum += p;
            }
            #pragma unroll
            for (int off = 8; off; off >>= 1)
                lsum += __shfl_xor_sync(0xffffffffu, lsum, off);
            l[rr] = l[rr] * alpha + lsum;
            m[rr] = mnew;
            #pragma unroll
            for (int j = 0; j < 8; ++j) o[rr][j] *= alpha;
            Ps[(r0 + rr) * 68 + (tx << 2) + 0] = s[rr][0];
            Ps[(r0 + rr) * 68 + (tx << 2) + 1] = s[rr][1];
            Ps[(r0 + rr) * 68 + (tx << 2) + 2] = s[rr][2];
            Ps[(r0 + rr) * 68 + (tx << 2) + 3] = s[rr][3];
        }
        __syncthreads();

        // O += P @ V  (4 rows x 8 cols per thread)
        #pragma unroll 2
        for (int k = 0; k < 64; ++k) {
            float vr[8];
            #pragma unroll
            for (int j = 0; j < 8; ++j) vr[j] = Vs[k * 132 + (tx << 3) + j];
            #pragma unroll
            for (int rr = 0; rr < 4; ++rr) {
                float pv = Ps[(r0 + rr) * 68 + k];
                #pragma unroll
                for (int j = 0; j < 8; ++j)
                    o[rr][j] = fmaf(pv, vr[j], o[rr][j]);
            }
        }
    }

    #pragma unroll
    for (int rr = 0; rr < 4; ++rr) {
        float inv = 1.f / l[rr];
        size_t t = (size_t)(b * S_ + (it << 6) + r0 + rr);
        float* op = outa + t * HID + h * D_ + (tx << 3);
        #pragma unroll
        for (int j = 0; j < 8; ++j) op[j] = o[rr][j] * inv;
    }
}

// ---------------------------------------------------------------------------
// Launch: QKV gemm -> rope -> (cache copy + scatter) -> attention -> O gemm
// Output layout: [attn_out T*HID][key_cache NSLOTS*KVH*D][value_cache ...]
// ---------------------------------------------------------------------------
extern "C" void kernel_launch(void* const* d_in, const int* in_sizes, int n_in,
                              void* d_out, int out_size)
{
    const float* hidden = (const float*)d_in[0];
    const float* cs     = (const float*)d_in[1];
    const float* sn     = (const float*)d_in[2];
    const float* w_qkv  = (const float*)d_in[3];
    const float* w_o    = (const float*)d_in[4];
    const float* kc_in  = (const float*)d_in[5];
    const float* vc_in  = (const float*)d_in[6];
    const int*   slots  = (const int*)d_in[7];

    float* out      = (float*)d_out;
    float* out_attn = out;
    float* out_kc   = out + (size_t)T_ * HID;
    float* out_vc   = out_kc + (size_t)NSLOTS * KVH_ * D_;

    float* qkv_buf; float* attn_buf;
    cudaGetSymbolAddress((void**)&qkv_buf, g_qkv);
    cudaGetSymbolAddress((void**)&attn_buf, g_attn);

    const size_t cache_bytes = (size_t)NSLOTS * KVH_ * D_ * sizeof(float);
    cudaMemcpyAsync(out_kc, kc_in, cache_bytes, cudaMemcpyDeviceToDevice, 0);
    cudaMemcpyAsync(out_vc, vc_in, cache_bytes, cudaMemcpyDeviceToDevice, 0);

    // QKV projection: [T,HID] @ [QKVW,HID]^T
    gemm_abT<<<dim3(QKVW / 128, T_ / 128), 256>>>(hidden, w_qkv, qkv_buf, T_, QKVW, HID);

    // RoPE on q + k heads
    rope_kernel<<<(T_ * 40 * 64) / 256, 256>>>(qkv_buf, cs, sn);

    // KV cache scatter
    scatter_kv<<<T_, 256>>>(qkv_buf, slots, out_kc, out_vc);

    // Flash attention
    static const int smem_bytes = ATT_SMEM_FLOATS * (int)sizeof(float);
    cudaFuncSetAttribute(attn_kernel, cudaFuncAttributeMaxDynamicSharedMemorySize, smem_bytes);
    attn_kernel<<<dim3(S_ / 64, H_, B_), 256, smem_bytes>>>(qkv_buf, attn_buf);

    // O projection: [T,HID] @ [HID,HID]^T
    gemm_abT<<<dim3(HID / 128, T_ / 128), 256>>>(attn_buf, w_o, out_attn, T_, HID, HID);
}

// round 2
// speedup vs baseline: 2.0618x; 2.0618x over previous
#include <cuda_runtime.h>
#include <cuda_bf16.h>
#include <cstdint>
#include <cstddef>

// Problem constants
#define B_   4
#define S_   1024
#define T_   4096            // B*S
#define HID  4096
#define H_   32
#define KVH_ 8
#define D_   128
#define ROT_ 64
#define QKVW 6144            // H*D + 2*KVH*D
#define NSLOTS 8192
#define SCALE_ 0.08838834764831845f   // 1/sqrt(128)

// Scratch (allocation-free rule: __device__ globals)
__device__ float g_qkv[(size_t)T_ * QKVW];        // QKV output (RoPE in place)
__device__ float g_attn[(size_t)T_ * HID];        // attention out, pre-O-proj
__device__ __nv_bfloat16 g_ah[(size_t)T_ * HID];  // activation hi (hidden, then attn)
__device__ __nv_bfloat16 g_al[(size_t)T_ * HID];  // activation lo
__device__ __nv_bfloat16 g_bh[(size_t)QKVW * HID];// weight hi (w_qkv, then w_o)
__device__ __nv_bfloat16 g_bl[(size_t)QKVW * HID];// weight lo

// ---------------------------------------------------------------------------
// Split fp32 -> bf16 hi + bf16 lo (residual). n divisible by 4.
// ---------------------------------------------------------------------------
__global__ __launch_bounds__(256) void split_bf16(
    const float* __restrict__ x, __nv_bfloat16* __restrict__ hi,
    __nv_bfloat16* __restrict__ lo, size_t n4)
{
    size_t i = (size_t)blockIdx.x * 256 + threadIdx.x;
    if (i >= n4) return;
    float4 v = ((const float4*)x)[i];
    __nv_bfloat16 hx = __float2bfloat16(v.x);
    __nv_bfloat16 hy = __float2bfloat16(v.y);
    __nv_bfloat16 hz = __float2bfloat16(v.z);
    __nv_bfloat16 hw = __float2bfloat16(v.w);
    __nv_bfloat162* hp = (__nv_bfloat162*)(hi + 4 * i);
    hp[0] = __nv_bfloat162(hx, hy);
    hp[1] = __nv_bfloat162(hz, hw);
    __nv_bfloat16 lx = __float2bfloat16(v.x - __bfloat162float(hx));
    __nv_bfloat16 ly = __float2bfloat16(v.y - __bfloat162float(hy));
    __nv_bfloat16 lz = __float2bfloat16(v.z - __bfloat162float(hz));
    __nv_bfloat16 lw = __float2bfloat16(v.w - __bfloat162float(hw));
    __nv_bfloat162* lp = (__nv_bfloat162*)(lo + 4 * i);
    lp[0] = __nv_bfloat162(lx, ly);
    lp[1] = __nv_bfloat162(lz, lw);
}

// ---------------------------------------------------------------------------
// bf16x3 tensor-core GEMM: C[M,N] = A[M,K] @ B[N,K]^T, fp32 out.
// A,B given as bf16 hi/lo pairs. 128x128x32 CTA tile, 8 warps (2x4),
// 3-stage cp.async pipeline, ldmatrix operand loads, mma.sync m16n8k16.
// ---------------------------------------------------------------------------
#define BKG 32
#define LDA 40                        // padded bf16 row stride (conflict-free)
#define TILE_E (128 * LDA)            // 5120 bf16 per matrix tile
#define STAGE_E (4 * TILE_E)          // Ah, Al, Bh, Bl
#define NSTAGE 3
#define GEMM_SMEM_BYTES (NSTAGE * STAGE_E * 2)

#define LDMX4(r0,r1,r2,r3,addr) \
    asm volatile("ldmatrix.sync.aligned.m8n8.x4.shared.b16 {%0,%1,%2,%3},[%4];" \
        : "=r"(r0),"=r"(r1),"=r"(r2),"=r"(r3) : "r"(addr))

#define MMA16816(d,a,b) \
    asm volatile("mma.sync.aligned.m16n8k16.row.col.f32.bf16.bf16.f32 " \
        "{%0,%1,%2,%3},{%4,%5,%6,%7},{%8,%9},{%0,%1,%2,%3};" \
        : "+f"(d[0]),"+f"(d[1]),"+f"(d[2]),"+f"(d[3]) \
        : "r"(a[0]),"r"(a[1]),"r"(a[2]),"r"(a[3]),"r"(b[0]),"r"(b[1]))

#define CPASYNC16(saddr,gptr) \
    asm volatile("cp.async.cg.shared.global [%0],[%1],16;" :: "r"(saddr),"l"(gptr))

__global__ __launch_bounds__(256, 1) void gemm_bf16x3(
    const __nv_bfloat16* __restrict__ Ah, const __nv_bfloat16* __restrict__ Al,
    const __nv_bfloat16* __restrict__ Bh, const __nv_bfloat16* __restrict__ Bl,
    float* __restrict__ C, int M, int N, int K)
{
    extern __shared__ __nv_bfloat16 smg[];
    const uint32_t sbase = (uint32_t)__cvta_generic_to_shared(smg);

    const int tid = threadIdx.x;
    const int lane = tid & 31, w = tid >> 5;
    const int wm = w >> 2, wn = w & 3;          // 2 x 4 warp grid
    const int bm = blockIdx.y << 7, bn = blockIdx.x << 7;

    // cp.async mapping: chunk c in [0,512): row=c>>2, seg=c&3 (16B each)
    const int r0c = tid >> 2, s0c = (tid & 3);        // chunk tid
    const int r1c = (tid + 256) >> 2, s1c = s0c;      // chunk tid+256

    const __nv_bfloat16* gA_h = Ah + (size_t)(bm + r0c) * K + s0c * 8;
    const __nv_bfloat16* gA_h2= Ah + (size_t)(bm + r1c) * K + s1c * 8;
    const __nv_bfloat16* gA_l = Al + (size_t)(bm + r0c) * K + s0c * 8;
    const __nv_bfloat16* gA_l2= Al + (size_t)(bm + r1c) * K + s1c * 8;
    const __nv_bfloat16* gB_h = Bh + (size_t)(bn + r0c) * K + s0c * 8;
    const __nv_bfloat16* gB_h2= Bh + (size_t)(bn + r1c) * K + s1c * 8;
    const __nv_bfloat16* gB_l = Bl + (size_t)(bn + r0c) * K + s0c * 8;
    const __nv_bfloat16* gB_l2= Bl + (size_t)(bn + r1c) * K + s1c * 8;

    const uint32_t so0 = (uint32_t)(r0c * LDA + s0c * 8) * 2;
    const uint32_t so1 = (uint32_t)(r1c * LDA + s1c * 8) * 2;

    #define LOAD_STAGE(st, kt) do {                                           \
        uint32_t sb = sbase + (uint32_t)(st) * (STAGE_E * 2);                 \
        int ko = (kt) * BKG;                                                  \
        CPASYNC16(sb + so0,                gA_h  + ko);                       \
        CPASYNC16(sb + so1,                gA_h2 + ko);                       \
        CPASYNC16(sb + TILE_E*2 + so0,     gA_l  + ko);                       \
        CPASYNC16(sb + TILE_E*2 + so1,     gA_l2 + ko);                       \
        CPASYNC16(sb + TILE_E*4 + so0,     gB_h  + ko);                       \
        CPASYNC16(sb + TILE_E*4 + so1,     gB_h2 + ko);                       \
        CPASYNC16(sb + TILE_E*6 + so0,     gB_l  + ko);                       \
        CPASYNC16(sb + TILE_E*6 + so1,     gB_l2 + ko);                       \
    } while (0)

    // ldmatrix per-thread element offsets (add ks*16 at use)
    uint32_t a_off[4], b_off[2];
    #pragma unroll
    for (int mf = 0; mf < 4; ++mf)
        a_off[mf] = (uint32_t)((wm * 64 + mf * 16 + (lane & 15)) * LDA
                               + (lane >> 4) * 8) * 2;
    #pragma unroll
    for (int nfp = 0; nfp < 2; ++nfp)
        b_off[nfp] = (uint32_t)((wn * 32 + nfp * 16 + ((lane >> 4) & 1) * 8
                                 + (lane & 7)) * LDA
                                + ((lane >> 3) & 1) * 8) * 2;

    float acc[4][4][4];
    #pragma unroll
    for (int i = 0; i < 4; ++i)
        #pragma unroll
        for (int j = 0; j < 4; ++j)
            #pragma unroll
            for (int k = 0; k < 4; ++k) acc[i][j][k] = 0.f;

    const int nk = K / BKG;   // 128
    LOAD_STAGE(0, 0);
    asm volatile("cp.async.commit_group;");
    LOAD_STAGE(1, 1);
    asm volatile("cp.async.commit_group;");

    for (int kt = 0; kt < nk; ++kt) {
        asm volatile("cp.async.wait_group 1;");
        __syncthreads();
        const int st = kt % NSTAGE;
        const uint32_t sb = sbase + (uint32_t)st * (STAGE_E * 2);

        #pragma unroll
        for (int ks = 0; ks < 2; ++ks) {
            const uint32_t kso = (uint32_t)(ks * 16) * 2;
            uint32_t ahf[4][4], alf[4][4], bhf[4][2], blf[4][2];
            #pragma unroll
            for (int mf = 0; mf < 4; ++mf) {
                LDMX4(ahf[mf][0], ahf[mf][1], ahf[mf][2], ahf[mf][3],
                      sb + a_off[mf] + kso);
                LDMX4(alf[mf][0], alf[mf][1], alf[mf][2], alf[mf][3],
                      sb + TILE_E*2 + a_off[mf] + kso);
            }
            #pragma unroll
            for (int nfp = 0; nfp < 2; ++nfp) {
                LDMX4(bhf[2*nfp][0], bhf[2*nfp][1], bhf[2*nfp+1][0], bhf[2*nfp+1][1],
                      sb + TILE_E*4 + b_off[nfp] + kso);
                LDMX4(blf[2*nfp][0], blf[2*nfp][1], blf[2*nfp+1][0], blf[2*nfp+1][1],
                      sb + TILE_E*6 + b_off[nfp] + kso);
            }
            #pragma unroll
            for (int mf = 0; mf < 4; ++mf)
                #pragma unroll
                for (int nf = 0; nf < 4; ++nf) {
                    MMA16816(acc[mf][nf], ahf[mf], bhf[nf]);
                    MMA16816(acc[mf][nf], ahf[mf], blf[nf]);
                    MMA16816(acc[mf][nf], alf[mf], bhf[nf]);
                }
        }
        if (kt + 2 < nk) LOAD_STAGE((kt + 2) % NSTAGE, kt + 2);
        asm volatile("cp.async.commit_group;");
    }

    // Epilogue
    const int cr = lane >> 2, cc = (lane & 3) << 1;
    #pragma unroll
    for (int mf = 0; mf < 4; ++mf) {
        #pragma unroll
        for (int nf = 0; nf < 4; ++nf) {
            const int row = bm + wm * 64 + mf * 16 + cr;
            const int col = bn + wn * 32 + nf * 8 + cc;
            float* p0 = C + (size_t)row * N + col;
            float* p1 = C + (size_t)(row + 8) * N + col;
            *(float2*)p0 = make_float2(acc[mf][nf][0], acc[mf][nf][1]);
            *(float2*)p1 = make_float2(acc[mf][nf][2], acc[mf][nf][3]);
        }
    }
}

// ---------------------------------------------------------------------------
// RoPE, in place on q (heads 0..31) and k (heads 32..39) of g_qkv.
// ---------------------------------------------------------------------------
__global__ __launch_bounds__(256) void rope_kernel(
    float* __restrict__ qkv, const float* __restrict__ cs, const float* __restrict__ sn)
{
    int idx = blockIdx.x * 256 + threadIdx.x;
    int i = idx & 63;
    int head = (idx >> 6) % 40;
    int t = idx / (64 * 40);
    float* base = qkv + (size_t)t * QKVW + head * D_;
    float c = cs[t * ROT_ + i];
    float s = sn[t * ROT_ + i];
    float x1 = base[i];
    float x2 = base[i + ROT_];
    base[i]        = x1 * c - x2 * s;
    base[i + ROT_] = x1 * s + x2 * c;
}

// ---------------------------------------------------------------------------
// Scatter roped K and raw V into output caches.
// ---------------------------------------------------------------------------
__global__ __launch_bounds__(256) void scatter_kv(
    const float* __restrict__ qkv, const int* __restrict__ slots,
    float* __restrict__ kc, float* __restrict__ vc)
{
    int t = blockIdx.x;
    int slot = slots[t];
    const float* k = qkv + (size_t)t * QKVW + (size_t)H_ * D_;
    const float* v = k + (size_t)KVH_ * D_;
    float* kd = kc + (size_t)slot * KVH_ * D_;
    float* vd = vc + (size_t)slot * KVH_ * D_;
    for (int i = threadIdx.x; i < KVH_ * D_; i += 256) {
        kd[i] = k[i];
        vd[i] = v[i];
    }
}

// ---------------------------------------------------------------------------
// Flash attention (fp32, online softmax). Same as R1 (verified correct).
// ---------------------------------------------------------------------------
#define ATT_SMEM_FLOATS (64*132 + 128*65 + 64*132 + 64*68)

__global__ __launch_bounds__(256) void attn_kernel(
    const float* __restrict__ qkv, float* __restrict__ outa)
{
    extern __shared__ float sm[];
    float* Qs  = sm;
    float* KsT = Qs + 64 * 132;
    float* Vs  = KsT + 128 * 65;
    float* Ps  = Vs + 64 * 132;

    const int it = blockIdx.x;
    const int h  = blockIdx.y;
    const int b  = blockIdx.z;
    const int kvh = h >> 2;
    const int tid = threadIdx.x, tx = tid & 15, ty = tid >> 4;
    const int r0 = ty << 2;

    const float* qg = qkv + (size_t)(b * S_ + (it << 6)) * QKVW + h * D_;
    const float* kg = qkv + (size_t)(b * S_) * QKVW + (size_t)H_ * D_ + kvh * D_;
    const float* vg = kg + (size_t)KVH_ * D_;

    for (int i = tid; i < 2048; i += 256) {
        int r = i >> 5, c = (i & 31) << 2;
        *(float4*)(Qs + r * 132 + c) = *(const float4*)(qg + (size_t)r * QKVW + c);
    }

    float m[4], l[4], o[4][8];
    #pragma unroll
    for (int rr = 0; rr < 4; ++rr) {
        m[rr] = -1e30f; l[rr] = 0.f;
        #pragma unroll
        for (int j = 0; j < 8; ++j) o[rr][j] = 0.f;
    }

    for (int jt = 0; jt <= it; ++jt) {
        __syncthreads();
        for (int i = tid; i < 2048; i += 256) {
            int r = i >> 5, c = (i & 31) << 2;
            float4 k4 = *(const float4*)(kg + (size_t)((jt << 6) + r) * QKVW + c);
            KsT[(c + 0) * 65 + r] = k4.x;
            KsT[(c + 1) * 65 + r] = k4.y;
            KsT[(c + 2) * 65 + r] = k4.z;
            KsT[(c + 3) * 65 + r] = k4.w;
            *(float4*)(Vs + r * 132 + c) =
                *(const float4*)(vg + (size_t)((jt << 6) + r) * QKVW + c);
        }
        __syncthreads();

        float s[4][4];
        #pragma unroll
        for (int rr = 0; rr < 4; ++rr)
            #pragma unroll
            for (int cc = 0; cc < 4; ++cc) s[rr][cc] = 0.f;

        #pragma unroll 4
        for (int k = 0; k < 128; ++k) {
            float kr[4];
            #pragma unroll
            for (int cc = 0; cc < 4; ++cc) kr[cc] = KsT[k * 65 + (tx << 2) + cc];
            #pragma unroll
            for (int rr = 0; rr < 4; ++rr) {
                float qv = Qs[(r0 + rr) * 132 + k];
                #pragma unroll
                for (int cc = 0; cc < 4; ++cc)
                    s[rr][cc] = fmaf(qv, kr[cc], s[rr][cc]);
            }
        }

        const bool diag = (jt == it);
        #pragma unroll
        for (int rr = 0; rr < 4; ++rr) {
            float mx = -1e30f;
            #pragma unroll
            for (int cc = 0; cc < 4; ++cc) {
                float v = s[rr][cc] * SCALE_;
                if (diag && ((tx << 2) + cc > r0 + rr)) v = -1e30f;
                s[rr][cc] = v;
                mx = fmaxf(mx, v);
            }
            #pragma unroll
            for (int off = 8; off; off >>= 1)
                mx = fmaxf(mx, __shfl_xor_sync(0xffffffffu, mx, off));
            float mnew = fmaxf(m[rr], mx);
            float alpha = __expf(m[rr] - mnew);
            float lsum = 0.f;
            #pragma unroll
            for (int cc = 0; cc < 4; ++cc) {
                float p = __expf(s[rr][cc] - mnew);
                s[rr][cc] = p;
                lsum += p;
            }
            #pragma unroll
            for (int off = 8; off; off >>= 1)
                lsum += __shfl_xor_sync(0xffffffffu, lsum, off);
            l[rr] = l[rr] * alpha + lsum;
            m[rr] = mnew;
            #pragma unroll
            for (int j = 0; j < 8; ++j) o[rr][j] *= alpha;
            Ps[(r0 + rr) * 68 + (tx << 2) + 0] = s[rr][0];
            Ps[(r0 + rr) * 68 + (tx << 2) + 1] = s[rr][1];
            Ps[(r0 + rr) * 68 + (tx << 2) + 2] = s[rr][2];
            Ps[(r0 + rr) * 68 + (tx << 2) + 3] = s[rr][3];
        }
        __syncthreads();

        #pragma unroll 2
        for (int k = 0; k < 64; ++k) {
            float vr[8];
            #pragma unroll
            for (int j = 0; j < 8; ++j) vr[j] = Vs[k * 132 + (tx << 3) + j];
            #pragma unroll
            for (int rr = 0; rr < 4; ++rr) {
                float pv = Ps[(r0 + rr) * 68 + k];
                #pragma unroll
                for (int j = 0; j < 8; ++j)
                    o[rr][j] = fmaf(pv, vr[j], o[rr][j]);
            }
        }
    }

    #pragma unroll
    for (int rr = 0; rr < 4; ++rr) {
        float inv = 1.f / l[rr];
        size_t t = (size_t)(b * S_ + (it << 6) + r0 + rr);
        float* op = outa + t * HID + h * D_ + (tx << 3);
        #pragma unroll
        for (int j = 0; j < 8; ++j) op[j] = o[rr][j] * inv;
    }
}

// ---------------------------------------------------------------------------
// Launch
// ---------------------------------------------------------------------------
extern "C" void kernel_launch(void* const* d_in, const int* in_sizes, int n_in,
                              void* d_out, int out_size)
{
    const float* hidden = (const float*)d_in[0];
    const float* cs     = (const float*)d_in[1];
    const float* sn     = (const float*)d_in[2];
    const float* w_qkv  = (const float*)d_in[3];
    const float* w_o    = (const float*)d_in[4];
    const float* kc_in  = (const float*)d_in[5];
    const float* vc_in  = (const float*)d_in[6];
    const int*   slots  = (const int*)d_in[7];

    float* out      = (float*)d_out;
    float* out_attn = out;
    float* out_kc   = out + (size_t)T_ * HID;
    float* out_vc   = out_kc + (size_t)NSLOTS * KVH_ * D_;

    float *qkv_buf, *attn_buf;
    __nv_bfloat16 *ah, *al, *bh, *bl;
    cudaGetSymbolAddress((void**)&qkv_buf, g_qkv);
    cudaGetSymbolAddress((void**)&attn_buf, g_attn);
    cudaGetSymbolAddress((void**)&ah, g_ah);
    cudaGetSymbolAddress((void**)&al, g_al);
    cudaGetSymbolAddress((void**)&bh, g_bh);
    cudaGetSymbolAddress((void**)&bl, g_bl);

    const size_t cache_bytes = (size_t)NSLOTS * KVH_ * D_ * sizeof(float);
    cudaMemcpyAsync(out_kc, kc_in, cache_bytes, cudaMemcpyDeviceToDevice, 0);
    cudaMemcpyAsync(out_vc, vc_in, cache_bytes, cudaMemcpyDeviceToDevice, 0);

    cudaFuncSetAttribute(gemm_bf16x3,
        cudaFuncAttributeMaxDynamicSharedMemorySize, GEMM_SMEM_BYTES);

    // Split hidden + w_qkv into bf16 hi/lo
    {
        size_t n4 = (size_t)T_ * HID / 4;
        split_bf16<<<(unsigned)((n4 + 255) / 256), 256>>>(hidden, ah, al, n4);
        size_t w4 = (size_t)QKVW * HID / 4;
        split_bf16<<<(unsigned)((w4 + 255) / 256), 256>>>(w_qkv, bh, bl, w4);
    }

    // QKV projection (tensor cores, bf16x3)
    gemm_bf16x3<<<dim3(QKVW / 128, T_ / 128), 256, GEMM_SMEM_BYTES>>>(
        ah, al, bh, bl, qkv_buf, T_, QKVW, HID);

    rope_kernel<<<(T_ * 40 * 64) / 256, 256>>>(qkv_buf, cs, sn);
    scatter_kv<<<T_, 256>>>(qkv_buf, slots, out_kc, out_vc);

    static const int att_smem = ATT_SMEM_FLOATS * (int)sizeof(float);
    cudaFuncSetAttribute(attn_kernel, cudaFuncAttributeMaxDynamicSharedMemorySize, att_smem);
    attn_kernel<<<dim3(S_ / 64, H_, B_), 256, att_smem>>>(qkv_buf, attn_buf);

    // Split attn output + w_o, then O projection
    {
        size_t n4 = (size_t)T_ * HID / 4;
        split_bf16<<<(unsigned)((n4 + 255) / 256), 256>>>(attn_buf, ah, al, n4);
        split_bf16<<<(unsigned)((n4 + 255) / 256), 256>>>(w_o, bh, bl, n4);
    }
    gemm_bf16x3<<<dim3(HID / 128, T_ / 128), 256, GEMM_SMEM_BYTES>>>(
        ah, al, bh, bl, out_attn, T_, HID, HID);
}